// round 17
// baseline (speedup 1.0000x reference)
#include <cuda_runtime.h>
#include <cstdint>

// Input:  x  (B=64, C=3, H=512, W+1=513) fp32; h_orig = x[b,0,0,512], w_orig = x[b,1,0,512]
// Output: (64, 3, 224, 224) fp32
// Resize shorter side to 256 (bilinear, half-pixel centers, rint), center-crop 224x224.
// R13: cp.async.bulk row-span staging into smem (in-flight data in SMEM, not regs),
// 2 output rows per block, taps via LDS, streaming stores.

#define OUT_H 224
#define OUT_W 224
#define IN_H 512
#define IN_W 513              // 512 data cols + metadata col
#define PLANE (IN_H * IN_W)
#define RESIZE_TO 256.0f
#define SPAN 456              // floats per staged plane (mult of 4 -> 16B); max need ~453
#define NPL 12                // 4 tap-rows x 3 channels

__device__ __forceinline__ uint32_t smem_u32(const void* p) {
    uint32_t a;
    asm("{ .reg .u64 t; cvta.to.shared.u64 t, %1; cvt.u32.u64 %0, t; }"
        : "=r"(a) : "l"(p));
    return a;
}

__device__ __forceinline__ void bulk_copy(uint32_t dst, const void* src,
                                          uint32_t bytes, uint32_t mbar) {
    asm volatile(
        "cp.async.bulk.shared::cluster.global.mbarrier::complete_tx::bytes "
        "[%0], [%1], %2, [%3];"
        :: "r"(dst), "l"(src), "r"(bytes), "r"(mbar) : "memory");
}

__global__ __launch_bounds__(OUT_W, 8) void center_crop_kernel(
    const float* __restrict__ x, float* __restrict__ out)
{
    __shared__ __align__(16) float s[NPL * SPAN + 4];
    __shared__ __align__(8) unsigned long long mbar;

    const int ypair = blockIdx.x;   // 0..111
    const int b = blockIdx.y;       // 0..63
    const int tx = threadIdx.x;     // 0..223

    if (tx == 0) {
        asm volatile("mbarrier.init.shared.b64 [%0], 1;"
                     :: "r"(smem_u32(&mbar)) : "memory");
    }
    __syncthreads();

    const float* img = x + b * (3 * PLANE);

    // ---- per-image params (uniform) ----
    const float h = img[IN_W - 1];
    const float w = img[PLANE + IN_W - 1];
    const float min_dim = fminf(h, w);
    const float scale = RESIZE_TO / min_dim;
    const float h_res = rintf(h * scale);
    const float w_res = rintf(w * scale);
    const float top  = rintf((h_res - (float)OUT_H) * 0.5f);
    const float left = rintf((w_res - (float)OUT_W) * 0.5f);
    const int hi = (int)h - 1;
    const int wi = (int)w - 1;

    // ---- tap rows for the 2 output rows (uniform) ----
    int rowA0, rowB0, rowA1, rowB1;
    float wy0, wy1;
    {
        const int y = ypair * 2;
        float sy = (((float)y + top) + 0.5f) * h / h_res - 0.5f;
        sy = fminf(fmaxf(sy, 0.0f), h - 1.0f);
        float y0f = floorf(sy);
        wy0 = sy - y0f;
        int y0 = max(0, min((int)y0f, hi));
        rowA0 = y0; rowB0 = min(y0 + 1, hi);

        float sy1 = (((float)(y + 1) + top) + 0.5f) * h / h_res - 0.5f;
        sy1 = fminf(fmaxf(sy1, 0.0f), h - 1.0f);
        float y1f = floorf(sy1);
        wy1 = sy1 - y1f;
        int y1 = max(0, min((int)y1f, hi));
        rowA1 = y1; rowB1 = min(y1 + 1, hi);
    }

    // ---- x scalars (uniform): x_first from tx=0, x_last base from tx=223 ----
    const float xmul = w / w_res;
    float sx0 = (left + 0.5f) * xmul - 0.5f;
    sx0 = fminf(fmaxf(sx0, 0.0f), w - 1.0f);
    const int x_first = max(0, min((int)floorf(sx0), wi));

    float sxl = ((223.0f + left) + 0.5f) * xmul - 0.5f;
    sxl = fminf(fmaxf(sxl, 0.0f), w - 1.0f);
    const int x_last0 = max(0, min((int)floorf(sxl), wi));
    const int xneed = x_last0 + 2 - x_first;     // floats needed from x_first

    // per-slot 16B alignment: global float index (row*513 + x_first) aligned down to 4
    const int g0 = rowA0 * IN_W + x_first, d0 = g0 & 3, st0 = g0 - d0;
    const int g1 = rowB0 * IN_W + x_first, d1 = g1 & 3, st1 = g1 - d1;
    const int g2 = rowA1 * IN_W + x_first, d2 = g2 & 3, st2 = g2 - d2;
    const int g3 = rowB1 * IN_W + x_first, d3 = g3 & 3, st3 = g3 - d3;
    const int cap = 512 - x_first;               // stay within data cols of the row
    const int l0 = min(min((d0 + xneed + 3) & ~3, (d0 + cap) & ~3), SPAN);
    const int l1 = min(min((d1 + xneed + 3) & ~3, (d1 + cap) & ~3), SPAN);
    const int l2 = min(min((d2 + xneed + 3) & ~3, (d2 + cap) & ~3), SPAN);
    const int l3 = min(min((d3 + xneed + 3) & ~3, (d3 + cap) & ~3), SPAN);

    // ---- issue copies (one thread) ----
    if (tx == 0) {
        const uint32_t mb = smem_u32(&mbar);
        const uint32_t sbase = smem_u32(s);
        const uint32_t totalB = (uint32_t)(3 * 4 * (l0 + l1 + l2 + l3));
        asm volatile("mbarrier.arrive.expect_tx.shared.b64 _, [%0], %1;"
                     :: "r"(mb), "r"(totalB) : "memory");
        #pragma unroll
        for (int c = 0; c < 3; c++) {
            bulk_copy(sbase + (uint32_t)((0 * 3 + c) * SPAN * 4), img + c * PLANE + st0, (uint32_t)(l0 * 4), mb);
            bulk_copy(sbase + (uint32_t)((1 * 3 + c) * SPAN * 4), img + c * PLANE + st1, (uint32_t)(l1 * 4), mb);
            bulk_copy(sbase + (uint32_t)((2 * 3 + c) * SPAN * 4), img + c * PLANE + st2, (uint32_t)(l2 * 4), mb);
            bulk_copy(sbase + (uint32_t)((3 * 3 + c) * SPAN * 4), img + c * PLANE + st3, (uint32_t)(l3 * 4), mb);
        }
    }

    // ---- zero 4-float pads after each staged span (weight-0 taps read finite 0) ----
    if (tx < 4) {
        const int lf = (tx == 0) ? l0 : (tx == 1) ? l1 : (tx == 2) ? l2 : l3;
        if (lf < SPAN) {
            #pragma unroll
            for (int c = 0; c < 3; c++) {
                float* p = s + (tx * 3 + c) * SPAN + lf;
                p[0] = 0.0f; p[1] = 0.0f; p[2] = 0.0f; p[3] = 0.0f;
            }
        }
    } else if (tx == 4) {
        s[NPL * SPAN] = 0.0f; s[NPL * SPAN + 1] = 0.0f;
        s[NPL * SPAN + 2] = 0.0f; s[NPL * SPAN + 3] = 0.0f;
    }

    // ---- per-thread column coordinate ----
    float src_x = (((float)tx + left) + 0.5f) * xmul - 0.5f;
    src_x = fminf(fmaxf(src_x, 0.0f), w - 1.0f);
    const float x0f = floorf(src_x);
    const float wx = src_x - x0f;
    int x0 = max(0, min((int)x0f, wi));
    const int xo = x0 - x_first;          // >= 0 (monotone)

    // ---- wait for staged data (acquire) ----
    {
        const uint32_t mb = smem_u32(&mbar);
        uint32_t done;
        do {
            asm volatile(
                "{\n\t.reg .pred p;\n\t"
                "mbarrier.try_wait.parity.acquire.cta.shared::cta.b64 p, [%1], %2, 0x989680;\n\t"
                "selp.b32 %0, 1, 0, p;\n\t}"
                : "=r"(done) : "r"(mb), "r"(0u) : "memory");
        } while (!done);
    }

    // ---- bilinear from smem ----
    const int jA0 = xo + d0, jB0 = xo + d1, jA1 = xo + d2, jB1 = xo + d3;
    const int out_base = b * (3 * OUT_H * OUT_W) + (ypair * 2) * OUT_W + tx;

    #pragma unroll
    for (int c = 0; c < 3; c++) {
        // output row 0: slots 0 (rowA0), 1 (rowB0)
        {
            const float* pa = s + (0 * 3 + c) * SPAN + jA0;
            const float* pb = s + (1 * 3 + c) * SPAN + jB0;
            const float v00 = pa[0], v01 = pa[1];
            const float v10 = pb[0], v11 = pb[1];
            const float t0 = v00 + wx * (v01 - v00);
            const float t1 = v10 + wx * (v11 - v10);
            __stcs(out + out_base + c * (OUT_H * OUT_W), t0 + wy0 * (t1 - t0));
        }
        // output row 1: slots 2 (rowA1), 3 (rowB1)
        {
            const float* pa = s + (2 * 3 + c) * SPAN + jA1;
            const float* pb = s + (3 * 3 + c) * SPAN + jB1;
            const float v00 = pa[0], v01 = pa[1];
            const float v10 = pb[0], v11 = pb[1];
            const float t0 = v00 + wx * (v01 - v00);
            const float t1 = v10 + wx * (v11 - v10);
            __stcs(out + out_base + c * (OUT_H * OUT_W) + OUT_W, t0 + wy1 * (t1 - t0));
        }
    }
}

extern "C" void kernel_launch(void* const* d_in, const int* in_sizes, int n_in,
                              void* d_out, int out_size)
{
    const float* x = (const float*)d_in[0];
    float* out = (float*)d_out;
    dim3 grid(OUT_H / 2, 64);
    dim3 block(OUT_W);
    center_crop_kernel<<<grid, block>>>(x, out);
}